// round 1
// baseline (speedup 1.0000x reference)
#include <cuda_runtime.h>
#include <math.h>
#include <stdint.h>

// ---------------------------------------------------------------------------
// Problem constants
// ---------------------------------------------------------------------------
#define NN      8192      // matrix dimension
#define MREAL   101       // real columns: y + 100 probes
#define MP      128       // padded columns (power of 2)
#define PITER   30        // CG iterations
#define KSPLIT  16        // k-dimension split for GEMM parallelism
#define KCHUNK  (NN / KSPLIT)       // 512
#define KT      32                  // k tile staged in smem
#define TILES_PER_BLOCK (KCHUNK/KT) // 16
#define ROWB    128                 // rows per GEMM block

// ---------------------------------------------------------------------------
// Scratch (static device globals; no allocation allowed)
// ---------------------------------------------------------------------------
__device__ float g_P[(size_t)MP * NN];                  // column-major [col][row], 4 MB
__device__ float g_R[(size_t)MP * NN];                  // 4 MB
__device__ float g_X[NN];                               // solution for column 0 (y)
__device__ float g_rs[MP];                              // residual norms^2
__device__ float g_Vpart[(size_t)KSPLIT * MP * NN];     // 64 MB GEMM partials
__device__ float g_alpha[PITER * MP];
__device__ float g_beta[PITER * MP];
__device__ float g_logdet;

// ---------------------------------------------------------------------------
// Packed f32x2 FMA (Blackwell FFMA2; ptxas only emits via PTX fma.rn.f32x2)
// ---------------------------------------------------------------------------
union F2U { float2 f; unsigned long long u; };

__device__ __forceinline__ float2 ffma2(float2 a, float2 b, float2 c) {
    F2U A, B, C, D;
    A.f = a; B.f = b; C.f = c;
    asm("fma.rn.f32x2 %0, %1, %2, %3;" : "=l"(D.u) : "l"(A.u), "l"(B.u), "l"(C.u));
    return D.f;
}

// ---------------------------------------------------------------------------
// Block reduce (256 threads, deterministic tree)
// ---------------------------------------------------------------------------
__device__ __forceinline__ float blockReduce256(float v, float* red) {
    int tid = threadIdx.x;
    red[tid] = v;
    __syncthreads();
#pragma unroll
    for (int s = 128; s > 0; s >>= 1) {
        if (tid < s) red[tid] += red[tid + s];
        __syncthreads();
    }
    float out = red[0];
    __syncthreads();
    return out;
}

// ---------------------------------------------------------------------------
// Init: P = R = B = [y | Z | 0-pad], X = 0
// ---------------------------------------------------------------------------
__global__ void k_init(const float* __restrict__ y, const float* __restrict__ Z) {
    int stride = gridDim.x * blockDim.x;
    for (int idx = blockIdx.x * blockDim.x + threadIdx.x; idx < MP * NN; idx += stride) {
        int col = idx >> 13;           // / NN
        int row = idx & (NN - 1);
        float v = 0.0f;
        if (col == 0)           v = y[row];
        else if (col <= 100)    v = Z[row * 100 + (col - 1)];
        g_P[idx] = v;
        g_R[idx] = v;
        if (col == 0) g_X[row] = 0.0f;
    }
}

// rs[j] = sum_i B[j][i]^2
__global__ void k_rsinit() {
    __shared__ float red[256];
    int j = blockIdx.x;
    const float* p = g_P + (size_t)j * NN;
    float s = 0.0f;
    for (int i = threadIdx.x; i < NN; i += 256) s += p[i] * p[i];
    s = blockReduce256(s, red);
    if (threadIdx.x == 0) g_rs[j] = s;
}

// ---------------------------------------------------------------------------
// GEMM: Vpart[ks] += K[rb:rb+128, kchunk] @ P[kchunk, 0:128]
// grid = 64 rowblocks x 16 ksplits = 1024 blocks, 256 threads
// Thread tile 8 rows x 8 cols, FFMA2 over column pairs.
// ---------------------------------------------------------------------------
__global__ void __launch_bounds__(256, 2)
k_gemm(const float* __restrict__ K) {
    __shared__ float ks[ROWB][KT + 1];   // [row][kk], pad 33 -> conflict-free
    __shared__ float pt[KT][MP + 4];     // [kk][col], pad 132

    int tid = threadIdx.x;
    int bid = blockIdx.x;
    int rb  = (bid & 63) * ROWB;
    int ksp = bid >> 6;                  // 0..KSPLIT-1
    int k0b = ksp * KCHUNK;

    // warp covers 8 tx x 4 ty  -> fewer smem phases
    int lane = tid & 31, wrp = tid >> 5;
    int tx = ((wrp & 1) << 3) + (lane & 7);   // 0..15
    int ty = ((wrp >> 1) << 2) + (lane >> 3); // 0..15
    int c0 = tx * 8, r0 = ty * 8;

    float2 acc[8][4];
#pragma unroll
    for (int i = 0; i < 8; i++)
#pragma unroll
        for (int c = 0; c < 4; c++) acc[i][c] = make_float2(0.0f, 0.0f);

    for (int t = 0; t < TILES_PER_BLOCK; t++) {
        int k0 = k0b + t * KT;
        // stage K: 128 rows x 32 k (coalesced float4, conflict-free stores)
#pragma unroll
        for (int it = 0; it < 4; it++) {
            int idx = tid + it * 256;
            int row = idx >> 3, q = idx & 7;
            float4 f = *(const float4*)(K + (size_t)(rb + row) * NN + k0 + q * 4);
            ks[row][q * 4 + 0] = f.x;
            ks[row][q * 4 + 1] = f.y;
            ks[row][q * 4 + 2] = f.z;
            ks[row][q * 4 + 3] = f.w;
        }
        // stage P (transposed into [kk][col])
#pragma unroll
        for (int it = 0; it < 4; it++) {
            int idx = tid + it * 256;
            int col = idx >> 3, q = idx & 7;
            float4 f = *(const float4*)(g_P + (size_t)col * NN + k0 + q * 4);
            pt[q * 4 + 0][col] = f.x;
            pt[q * 4 + 1][col] = f.y;
            pt[q * 4 + 2][col] = f.z;
            pt[q * 4 + 3][col] = f.w;
        }
        __syncthreads();

#pragma unroll
        for (int kk = 0; kk < KT; kk++) {
            float4 pA = *(const float4*)&pt[kk][c0];
            float4 pB = *(const float4*)&pt[kk][c0 + 4];
            float2 b0 = make_float2(pA.x, pA.y);
            float2 b1 = make_float2(pA.z, pA.w);
            float2 b2 = make_float2(pB.x, pB.y);
            float2 b3 = make_float2(pB.z, pB.w);
#pragma unroll
            for (int i = 0; i < 8; i++) {
                float a = ks[r0 + i][kk];
                float2 a2 = make_float2(a, a);
                acc[i][0] = ffma2(a2, b0, acc[i][0]);
                acc[i][1] = ffma2(a2, b1, acc[i][1]);
                acc[i][2] = ffma2(a2, b2, acc[i][2]);
                acc[i][3] = ffma2(a2, b3, acc[i][3]);
            }
        }
        __syncthreads();
    }

    // epilogue: thread owns 8 consecutive rows per column -> 2x STG.128 per col
    float* vp = g_Vpart + (size_t)ksp * MP * NN;
#pragma unroll
    for (int cp = 0; cp < 4; cp++) {
        int ce = c0 + 2 * cp;
        float4 lo, hi;
        lo.x = acc[0][cp].x; lo.y = acc[1][cp].x; lo.z = acc[2][cp].x; lo.w = acc[3][cp].x;
        hi.x = acc[4][cp].x; hi.y = acc[5][cp].x; hi.z = acc[6][cp].x; hi.w = acc[7][cp].x;
        *(float4*)(vp + (size_t)ce * NN + rb + r0)     = lo;
        *(float4*)(vp + (size_t)ce * NN + rb + r0 + 4) = hi;
        lo.x = acc[0][cp].y; lo.y = acc[1][cp].y; lo.z = acc[2][cp].y; lo.w = acc[3][cp].y;
        hi.x = acc[4][cp].y; hi.y = acc[5][cp].y; hi.z = acc[6][cp].y; hi.w = acc[7][cp].y;
        *(float4*)(vp + (size_t)(ce + 1) * NN + rb + r0)     = lo;
        *(float4*)(vp + (size_t)(ce + 1) * NN + rb + r0 + 4) = hi;
    }
}

// ---------------------------------------------------------------------------
// CG update: one block per real column. Sums Vpart, computes pv, alpha,
// updates X (col 0 only), R, rs, beta, P. Records alpha/beta.
// ---------------------------------------------------------------------------
__global__ void k_update(int it) {
    __shared__ float red[256];
    __shared__ float sc[2];
    const int E = NN / 256;  // 32 rows per thread

    int j = blockIdx.x;
    int tid = threadIdx.x;
    const float* Pc = g_P + (size_t)j * NN;
    const float* Rc = g_R + (size_t)j * NN;

    float p[E], v[E], r[E];
    float pv = 0.0f;
#pragma unroll
    for (int t = 0; t < E; t++) {
        int row = t * 256 + tid;
        float s = 0.0f;
#pragma unroll
        for (int sp = 0; sp < KSPLIT; sp++)
            s += g_Vpart[((size_t)sp * MP + j) * NN + row];
        v[t] = s;
        p[t] = Pc[row];
        pv += p[t] * s;
    }
    pv = blockReduce256(pv, red);
    float rs_old = g_rs[j];
    if (tid == 0) sc[0] = rs_old / pv;
    __syncthreads();
    float alpha = sc[0];

    float rr = 0.0f;
#pragma unroll
    for (int t = 0; t < E; t++) {
        int row = t * 256 + tid;
        float rv = Rc[row] - alpha * v[t];
        r[t] = rv;
        rr += rv * rv;
    }
    if (j == 0) {
#pragma unroll
        for (int t = 0; t < E; t++) {
            int row = t * 256 + tid;
            g_X[row] += alpha * p[t];
        }
    }
    rr = blockReduce256(rr, red);
    if (tid == 0) {
        float beta = rr / rs_old;
        sc[1] = beta;
        g_rs[j] = rr;
        g_alpha[it * MP + j] = alpha;
        g_beta[it * MP + j]  = beta;
    }
    __syncthreads();
    float beta = sc[1];

    float* Pw = g_P + (size_t)j * NN;
    float* Rw = g_R + (size_t)j * NN;
#pragma unroll
    for (int t = 0; t < E; t++) {
        int row = t * 256 + tid;
        Pw[row] = r[t] + beta * p[t];
        Rw[row] = r[t];
    }
}

// ---------------------------------------------------------------------------
// SLQ logdet: per probe, build 30x30 tridiagonal T from (alpha,beta) and run
// TQLI (implicit-shift QL), tracking only the first row of the eigenvector
// matrix. quad = sum z0_k^2 * log(max(lam_k,1e-12)); logdet = N * mean(quad).
// ---------------------------------------------------------------------------
__device__ void tqli30(double* d, double* e, double* z) {
    const int n = PITER;
    for (int l = 0; l < n; l++) {
        int iter = 0;
        int m;
        do {
            for (m = l; m < n - 1; m++) {
                double dd = fabs(d[m]) + fabs(d[m + 1]);
                if (fabs(e[m]) <= 2.3e-16 * dd) break;
            }
            if (m != l) {
                if (iter++ == 64) break;
                double g = (d[l + 1] - d[l]) / (2.0 * e[l]);
                double rr = sqrt(g * g + 1.0);
                double sg = (g >= 0.0) ? rr : -rr;
                g = d[m] - d[l] + e[l] / (g + sg);
                double s = 1.0, c = 1.0, p = 0.0;
                bool under = false;
                for (int i = m - 1; i >= l; i--) {
                    double f = s * e[i];
                    double b = c * e[i];
                    double r = sqrt(f * f + g * g);
                    e[i + 1] = r;
                    if (r == 0.0) {
                        d[i + 1] -= p;
                        e[m] = 0.0;
                        under = true;
                        break;
                    }
                    s = f / r; c = g / r;
                    g = d[i + 1] - p;
                    r = (d[i] - g) * s + 2.0 * c * b;
                    p = s * r;
                    d[i + 1] = g + p;
                    g = c * r - b;
                    double zi = z[i], zi1 = z[i + 1];
                    z[i + 1] = s * zi + c * zi1;
                    z[i]     = c * zi - s * zi1;
                }
                if (under) continue;
                d[l] -= p;
                e[l] = g;
                e[m] = 0.0;
            }
        } while (m != l);
    }
}

__global__ void k_logdet() {
    __shared__ double qsum[128];
    int tid = threadIdx.x;
    double quad = 0.0;
    if (tid < 100) {
        int j = tid + 1;  // probe columns are 1..100
        double d[PITER], e[PITER], z[PITER];
        double pa = 1.0, pb = 0.0;
        for (int k = 0; k < PITER; k++) {
            double a = (double)g_alpha[k * MP + j];
            double b = (double)g_beta[k * MP + j];
            d[k] = 1.0 / a + ((k > 0) ? pb / pa : 0.0);
            e[k] = (k < PITER - 1) ? sqrt(b) / a : 0.0;
            z[k] = (k == 0) ? 1.0 : 0.0;
            pa = a; pb = b;
        }
        tqli30(d, e, z);
        for (int k = 0; k < PITER; k++) {
            double lam = d[k] < 1e-12 ? 1e-12 : d[k];
            quad += z[k] * z[k] * log(lam);
        }
    }
    qsum[tid] = quad;
    __syncthreads();
    if (tid == 0) {
        double s = 0.0;
        for (int i = 0; i < 100; i++) s += qsum[i];
        g_logdet = (float)((double)NN * s / 100.0);
    }
}

// ---------------------------------------------------------------------------
// Final: out = -0.5 * (y . X) - 0.5 * logdet - N/2 * log(2*pi)
// ---------------------------------------------------------------------------
__global__ void k_final(const float* __restrict__ y, float* __restrict__ out) {
    __shared__ float red[256];
    float s = 0.0f;
    for (int i = threadIdx.x; i < NN; i += 256) s += y[i] * g_X[i];
    s = blockReduce256(s, red);
    if (threadIdx.x == 0) {
        const double LOG2PI = 1.8378770664093454836;
        double r = -0.5 * (double)s - 0.5 * (double)g_logdet - 0.5 * (double)NN * LOG2PI;
        out[0] = (float)r;
    }
}

// ---------------------------------------------------------------------------
// Launch
// ---------------------------------------------------------------------------
extern "C" void kernel_launch(void* const* d_in, const int* in_sizes, int n_in,
                              void* d_out, int out_size) {
    const float* K = (const float*)d_in[0];   // Knn_noise [8192, 8192]
    const float* y = (const float*)d_in[1];   // y [8192]
    const float* Z = (const float*)d_in[2];   // Z [8192, 100]
    float* out = (float*)d_out;

    k_init<<<512, 256>>>(y, Z);
    k_rsinit<<<MREAL, 256>>>();
    for (int it = 0; it < PITER; it++) {
        k_gemm<<<64 * KSPLIT, 256>>>(K);
        k_update<<<MREAL, 256>>>(it);
    }
    k_logdet<<<1, 128>>>();
    k_final<<<1, 256>>>(y, out);
}

// round 3
// speedup vs baseline: 1.8777x; 1.8777x over previous
#include <cuda_runtime.h>
#include <cuda_fp16.h>
#include <math.h>
#include <stdint.h>

// ---------------------------------------------------------------------------
// Problem constants
// ---------------------------------------------------------------------------
#define NN      8192
#define MREAL   101
#define MP      128
#define PITER   30
#define KSPLIT  2
#define KCHUNK  (NN / KSPLIT)        // 4096
#define KT      32                   // k per pipeline stage
#define KITERS  (KCHUNK / KT)        // 128
#define NSTG    4
#define TILEH   (128 * KT * 2)       // 8192 B: one 128x32 fp16 tile
#define STAGE_B (4 * TILEH)          // 32768 B: Ahi, Alo, Bhi, Blo
#define SMEM_DYN (NSTG * STAGE_B)    // 131072 B

// ---------------------------------------------------------------------------
// Scratch (static device globals; no allocation allowed)
// ---------------------------------------------------------------------------
__device__ __half g_Khi16[(size_t)NN * NN];     // 128 MB
__device__ __half g_Klo16[(size_t)NN * NN];     // 128 MB
__device__ __half g_Ph16[(size_t)MP * NN];      // scaled P hi, col-major
__device__ __half g_Pl16[(size_t)MP * NN];      // scaled P lo
__device__ float  g_R[(size_t)MP * NN];
__device__ float  g_X[NN];
__device__ float  g_rs[MP];
__device__ float  g_pscale[MP];                 // power-of-2 column scale
__device__ float  g_Vpart[(size_t)KSPLIT * MP * NN];  // 8 MB
__device__ float  g_alpha[PITER * MP];
__device__ float  g_beta[PITER * MP];
__device__ float  g_logdet;

// ---------------------------------------------------------------------------
// PTX helpers (family-portable only: ldmatrix / mma.sync / cp.async)
// ---------------------------------------------------------------------------
__device__ __forceinline__ uint32_t smem_u32(const void* p) {
    uint32_t a;
    asm("{ .reg .u64 t; cvta.to.shared.u64 t, %1; cvt.u32.u64 %0, t; }"
        : "=r"(a) : "l"(p));
    return a;
}

__device__ __forceinline__ void ldsm_x4(uint32_t (&r)[4], uint32_t addr) {
    asm volatile("ldmatrix.sync.aligned.m8n8.x4.shared.b16 {%0,%1,%2,%3}, [%4];"
        : "=r"(r[0]), "=r"(r[1]), "=r"(r[2]), "=r"(r[3]) : "r"(addr));
}

__device__ __forceinline__ void mma16816(float (&d)[4], const uint32_t (&a)[4],
                                         uint32_t b0, uint32_t b1) {
    asm volatile("mma.sync.aligned.m16n8k16.row.col.f32.f16.f16.f32 "
        "{%0,%1,%2,%3}, {%4,%5,%6,%7}, {%8,%9}, {%0,%1,%2,%3};"
        : "+f"(d[0]), "+f"(d[1]), "+f"(d[2]), "+f"(d[3])
        : "r"(a[0]), "r"(a[1]), "r"(a[2]), "r"(a[3]), "r"(b0), "r"(b1));
}

#define CPASYNC16(dst, src) \
    asm volatile("cp.async.cg.shared.global [%0], [%1], 16;" \
                 :: "r"(dst), "l"(__cvta_generic_to_global(src)) : "memory")

// Conflict-free swizzle for 64B rows (r = row 0..127, ch = 16B chunk 0..3)
#define SWZ(r, ch) (((r) << 6) + ((((ch) ^ (((r) >> 1) & 3))) << 4))

// ---------------------------------------------------------------------------
// Block reduce
// ---------------------------------------------------------------------------
template <int BS>
__device__ __forceinline__ float blockReduce(float v, float* red) {
    int tid = threadIdx.x;
    red[tid] = v;
    __syncthreads();
#pragma unroll
    for (int s = BS / 2; s > 0; s >>= 1) {
        if (tid < s) red[tid] += red[tid + s];
        __syncthreads();
    }
    float out = red[0];
    __syncthreads();
    return out;
}

// ---------------------------------------------------------------------------
// Split K into fp16 hi + fp16 lo (once per launch)
// ---------------------------------------------------------------------------
__global__ void k_split(const float* __restrict__ K) {
    size_t i0 = (size_t)blockIdx.x * blockDim.x + threadIdx.x;
    size_t stride = (size_t)gridDim.x * blockDim.x;
    size_t n8 = (size_t)NN * NN / 8;
    for (size_t i = i0; i < n8; i += stride) {
        float4 a = ((const float4*)K)[2 * i];
        float4 b = ((const float4*)K)[2 * i + 1];
        float v[8] = {a.x, a.y, a.z, a.w, b.x, b.y, b.z, b.w};
        union { __half h[8]; uint4 u; } H, L;
#pragma unroll
        for (int j = 0; j < 8; j++) {
            __half hh = __float2half_rn(v[j]);
            H.h[j] = hh;
            L.h[j] = __float2half_rn(v[j] - __half2float(hh));
        }
        ((uint4*)g_Khi16)[i] = H.u;
        ((uint4*)g_Klo16)[i] = L.u;
    }
}

// ---------------------------------------------------------------------------
// Init: B = [y | Z | 0-pad]; Ph/Pl = fp16 split of B (scale 1), R = B, X = 0
// ---------------------------------------------------------------------------
__global__ void k_init(const float* __restrict__ y, const float* __restrict__ Z) {
    int stride = gridDim.x * blockDim.x;
    for (int idx = blockIdx.x * blockDim.x + threadIdx.x; idx < MP * NN; idx += stride) {
        int col = idx >> 13;
        int row = idx & (NN - 1);
        float v = 0.0f;
        if (col == 0)        v = y[row];
        else if (col <= 100) v = Z[row * 100 + (col - 1)];
        __half h = __float2half_rn(v);
        g_Ph16[idx] = h;
        g_Pl16[idx] = __float2half_rn(v - __half2float(h));
        g_R[idx] = v;
        if (col == 0) g_X[row] = 0.0f;
        if (idx < MP) g_pscale[idx] = 1.0f;
    }
}

__global__ void k_rsinit() {
    __shared__ float red[256];
    int j = blockIdx.x;
    const float* p = g_R + (size_t)j * NN;
    float s = 0.0f;
    for (int i = threadIdx.x; i < NN; i += 256) s += p[i] * p[i];
    s = blockReduce<256>(s, red);
    if (threadIdx.x == 0) g_rs[j] = s;
}

// ---------------------------------------------------------------------------
// fp16-split HMMA GEMM: Vpart[ksp] = K[rb:rb+128, kchunk] @ Pscaled
// 3 products: Ahi*Bhi + Ahi*Blo + Alo*Bhi, fp32 accumulate.
// 256 threads, warp grid 4m x 2n, warp tile 32x64, 4-stage cp.async pipe.
// ---------------------------------------------------------------------------
__device__ __forceinline__ void issue_stage(uint32_t sb, int s, int rb, int k0, int tid) {
    uint32_t st = sb + s * STAGE_B;
#pragma unroll
    for (int m = 0; m < 2; m++) {
        int idx = m * 256 + tid;
        int r = idx >> 2, ch = idx & 3;
        uint32_t d = st + SWZ(r, ch);
        const __half* pa = g_Khi16 + (size_t)(rb + r) * NN + k0 + ch * 8;
        const __half* pb = g_Klo16 + (size_t)(rb + r) * NN + k0 + ch * 8;
        const __half* pc = g_Ph16 + (size_t)r * NN + k0 + ch * 8;
        const __half* pd = g_Pl16 + (size_t)r * NN + k0 + ch * 8;
        CPASYNC16(d, pa);
        CPASYNC16(d + TILEH, pb);
        CPASYNC16(d + 2 * TILEH, pc);
        CPASYNC16(d + 3 * TILEH, pd);
    }
    asm volatile("cp.async.commit_group;" ::: "memory");
}

__global__ void __launch_bounds__(256, 1) k_gemm_mma() {
    extern __shared__ char smem[];
    uint32_t sb = smem_u32(smem);
    int tid = threadIdx.x, lane = tid & 31, w = tid >> 5;
    int wm = w & 3, wn = w >> 2;
    int bid = blockIdx.x;
    int rb = (bid & 63) * 128;
    int ksp = bid >> 6;
    int kbase = ksp * KCHUNK;

    float acc[2][8][4];
#pragma unroll
    for (int mi = 0; mi < 2; mi++)
#pragma unroll
        for (int nj = 0; nj < 8; nj++)
#pragma unroll
            for (int q = 0; q < 4; q++) acc[mi][nj][q] = 0.0f;

    issue_stage(sb, 0, rb, kbase, tid);
    issue_stage(sb, 1, rb, kbase + KT, tid);
    issue_stage(sb, 2, rb, kbase + 2 * KT, tid);

    int rA = wm * 32 + (lane & 15);
    int rB = wn * 64 + (lane & 15);
    int chHalf = lane >> 4;

    for (int t = 0; t < KITERS; t++) {
        if (t < KITERS - 2)       asm volatile("cp.async.wait_group 2;" ::: "memory");
        else if (t == KITERS - 2) asm volatile("cp.async.wait_group 1;" ::: "memory");
        else                      asm volatile("cp.async.wait_group 0;" ::: "memory");
        __syncthreads();
        if (t + 3 < KITERS) issue_stage(sb, (t + 3) & 3, rb, kbase + (t + 3) * KT, tid);

        uint32_t st = sb + (t & 3) * STAGE_B;
#pragma unroll
        for (int kk = 0; kk < 2; kk++) {
            int ch = kk * 2 + chHalf;
            uint32_t ah[2][4], al[2][4], bh[4][4], bl[4][4];
            ldsm_x4(ah[0], st + SWZ(rA, ch));
            ldsm_x4(ah[1], st + SWZ(rA + 16, ch));
            ldsm_x4(al[0], st + TILEH + SWZ(rA, ch));
            ldsm_x4(al[1], st + TILEH + SWZ(rA + 16, ch));
#pragma unroll
            for (int nb = 0; nb < 4; nb++) {
                ldsm_x4(bh[nb], st + 2 * TILEH + SWZ(rB + nb * 16, ch));
                ldsm_x4(bl[nb], st + 3 * TILEH + SWZ(rB + nb * 16, ch));
            }
#pragma unroll
            for (int mi = 0; mi < 2; mi++)
#pragma unroll
                for (int nj = 0; nj < 8; nj++) {
                    int nb = nj >> 1, sel = nj & 1;
                    uint32_t bh0 = bh[nb][sel], bh1 = bh[nb][sel + 2];
                    uint32_t bl0 = bl[nb][sel], bl1 = bl[nb][sel + 2];
                    mma16816(acc[mi][nj], ah[mi], bh0, bh1);
                    mma16816(acc[mi][nj], ah[mi], bl0, bl1);
                    mma16816(acc[mi][nj], al[mi], bh0, bh1);
                }
        }
    }

    // epilogue: scatter fp32 accumulators to Vpart (col-major [col][row])
    float* vp = g_Vpart + (size_t)ksp * MP * NN;
    int row0 = rb + wm * 32 + (lane >> 2);
    int col0 = wn * 64 + (lane & 3) * 2;
#pragma unroll
    for (int mi = 0; mi < 2; mi++)
#pragma unroll
        for (int nj = 0; nj < 8; nj++) {
            int r_ = row0 + mi * 16;
            int c_ = col0 + nj * 8;
            vp[(size_t)c_ * NN + r_]           = acc[mi][nj][0];
            vp[(size_t)(c_ + 1) * NN + r_]     = acc[mi][nj][1];
            vp[(size_t)c_ * NN + r_ + 8]       = acc[mi][nj][2];
            vp[(size_t)(c_ + 1) * NN + r_ + 8] = acc[mi][nj][3];
        }
}

// ---------------------------------------------------------------------------
// CG update: one block (1024 threads) per real column, with power-of-2
// column scaling. Stored P is Ps = c*P_true; GEMM produced Vs = c*V_true.
// ---------------------------------------------------------------------------
__global__ void k_update(int it) {
    __shared__ float red[1024];
    const int E = NN / 1024;  // 8

    int j = blockIdx.x;
    int tid = threadIdx.x;
    float c = g_pscale[j];
    const __half* Phc = g_Ph16 + (size_t)j * NN;
    const __half* Plc = g_Pl16 + (size_t)j * NN;
    const float* Rc = g_R + (size_t)j * NN;
    const float* V0 = g_Vpart + (size_t)j * NN;
    const float* V1 = g_Vpart + ((size_t)MP + j) * NN;

    float p[E], v[E], r[E];
    float pv = 0.0f;
#pragma unroll
    for (int t = 0; t < E; t++) {
        int row = t * 1024 + tid;
        float s = V0[row] + V1[row];
        v[t] = s;
        p[t] = __half2float(Phc[row]) + __half2float(Plc[row]);
        pv += p[t] * s;
    }
    pv = blockReduce<1024>(pv, red);           // = sum Ps*Vs = c^2 * (P.V)
    float rs_old = g_rs[j];
    float alpha = rs_old * c * c / pv;         // true alpha
    float aoc = alpha / c;

    float rr = 0.0f;
#pragma unroll
    for (int t = 0; t < E; t++) {
        int row = t * 1024 + tid;
        float rv = Rc[row] - aoc * v[t];       // R - alpha*V_true
        r[t] = rv;
        rr += rv * rv;
    }
    if (j == 0) {
#pragma unroll
        for (int t = 0; t < E; t++) {
            int row = t * 1024 + tid;
            g_X[row] += aoc * p[t];            // X + alpha*P_true
        }
    }
    rr = blockReduce<1024>(rr, red);
    float beta = rr / rs_old;
    // new power-of-2 scale so entries of c2*Pnew are O(1)
    float c2 = exp2f(-rintf(0.5f * log2f(rr * (1.0f / (float)NN))));
    if (tid == 0) {
        g_rs[j] = rr;
        g_alpha[it * MP + j] = alpha;
        g_beta[it * MP + j]  = beta;
        g_pscale[j] = c2;
    }
    float boc = beta / c;

    __half* Phw = g_Ph16 + (size_t)j * NN;
    __half* Plw = g_Pl16 + (size_t)j * NN;
    float* Rw = g_R + (size_t)j * NN;
#pragma unroll
    for (int t = 0; t < E; t++) {
        int row = t * 1024 + tid;
        float pn = r[t] + boc * p[t];          // true new P
        float ps = c2 * pn;                    // scaled
        __half h = __float2half_rn(ps);
        Phw[row] = h;
        Plw[row] = __float2half_rn(ps - __half2float(h));
        Rw[row] = r[t];
    }
}

// ---------------------------------------------------------------------------
// SLQ logdet (TQLI on 30x30 tridiagonal, first-row eigenvector weights)
// ---------------------------------------------------------------------------
__device__ void tqli30(double* d, double* e, double* z) {
    const int n = PITER;
    for (int l = 0; l < n; l++) {
        int iter = 0;
        int m;
        do {
            for (m = l; m < n - 1; m++) {
                double dd = fabs(d[m]) + fabs(d[m + 1]);
                if (fabs(e[m]) <= 2.3e-16 * dd) break;
            }
            if (m != l) {
                if (iter++ == 64) break;
                double g = (d[l + 1] - d[l]) / (2.0 * e[l]);
                double rr = sqrt(g * g + 1.0);
                double sg = (g >= 0.0) ? rr : -rr;
                g = d[m] - d[l] + e[l] / (g + sg);
                double s = 1.0, cc = 1.0, p = 0.0;
                bool under = false;
                for (int i = m - 1; i >= l; i--) {
                    double f = s * e[i];
                    double b = cc * e[i];
                    double rq = sqrt(f * f + g * g);
                    e[i + 1] = rq;
                    if (rq == 0.0) {
                        d[i + 1] -= p;
                        e[m] = 0.0;
                        under = true;
                        break;
                    }
                    s = f / rq; cc = g / rq;
                    g = d[i + 1] - p;
                    rq = (d[i] - g) * s + 2.0 * cc * b;
                    p = s * rq;
                    d[i + 1] = g + p;
                    g = cc * rq - b;
                    double zi = z[i], zi1 = z[i + 1];
                    z[i + 1] = s * zi + cc * zi1;
                    z[i]     = cc * zi - s * zi1;
                }
                if (under) continue;
                d[l] -= p;
                e[l] = g;
                e[m] = 0.0;
            }
        } while (m != l);
    }
}

__global__ void k_logdet() {
    __shared__ double qsum[128];
    int tid = threadIdx.x;
    double quad = 0.0;
    if (tid < 100) {
        int j = tid + 1;
        double d[PITER], e[PITER], z[PITER];
        double pa = 1.0, pb = 0.0;
        for (int k = 0; k < PITER; k++) {
            double a = (double)g_alpha[k * MP + j];
            double b = (double)g_beta[k * MP + j];
            d[k] = 1.0 / a + ((k > 0) ? pb / pa : 0.0);
            e[k] = (k < PITER - 1) ? sqrt(b) / a : 0.0;
            z[k] = (k == 0) ? 1.0 : 0.0;
            pa = a; pb = b;
        }
        tqli30(d, e, z);
        for (int k = 0; k < PITER; k++) {
            double lam = d[k] < 1e-12 ? 1e-12 : d[k];
            quad += z[k] * z[k] * log(lam);
        }
    }
    qsum[tid] = quad;
    __syncthreads();
    if (tid == 0) {
        double s = 0.0;
        for (int i = 0; i < 100; i++) s += qsum[i];
        g_logdet = (float)((double)NN * s / 100.0);
    }
}

__global__ void k_final(const float* __restrict__ y, float* __restrict__ out) {
    __shared__ float red[256];
    float s = 0.0f;
    for (int i = threadIdx.x; i < NN; i += 256) s += y[i] * g_X[i];
    s = blockReduce<256>(s, red);
    if (threadIdx.x == 0) {
        const double LOG2PI = 1.8378770664093454836;
        double r = -0.5 * (double)s - 0.5 * (double)g_logdet - 0.5 * (double)NN * LOG2PI;
        out[0] = (float)r;
    }
}

// ---------------------------------------------------------------------------
// Launch
// ---------------------------------------------------------------------------
extern "C" void kernel_launch(void* const* d_in, const int* in_sizes, int n_in,
                              void* d_out, int out_size) {
    const float* K = (const float*)d_in[0];
    const float* y = (const float*)d_in[1];
    const float* Z = (const float*)d_in[2];
    float* out = (float*)d_out;

    cudaFuncSetAttribute(k_gemm_mma, cudaFuncAttributeMaxDynamicSharedMemorySize, SMEM_DYN);

    k_split<<<4096, 256>>>(K);
    k_init<<<512, 256>>>(y, Z);
    k_rsinit<<<MREAL, 256>>>();
    for (int it = 0; it < PITER; it++) {
        k_gemm_mma<<<64 * KSPLIT, 256, SMEM_DYN>>>();
        k_update<<<MREAL, 1024>>>(it);
    }
    k_logdet<<<1, 128>>>();
    k_final<<<1, 256>>>(y, out);
}